// round 2
// baseline (speedup 1.0000x reference)
#include <cuda_runtime.h>

#define BB   4
#define NTOK 4096
#define CC   256
#define NHH  8
#define HDD  32
#define LL   9
#define PP   64
#define TT   4096

// ---------------- scratch ----------------
__device__ float g_qraw [BB*NTOK*CC];
__device__ float g_kvraw[BB*NTOK*2*CC];
__device__ float g_qs   [BB*NTOK*CC];
__device__ float g_qn   [BB*NTOK*CC];
__device__ float g_kn   [BB*NTOK*CC];
__device__ float g_v    [BB*NTOK*CC];
__device__ float g_xs   [BB*NTOK*CC];
__device__ float g_pln  [BB*PP*CC];
__device__ float g_kpT  [BB*NHH*HDD*PP];   // [b][h][d][p]
__device__ float g_vpl  [BB*NHH*PP*HDD];   // [b][h][p][d]
__device__ float g_cpb  [TT*NHH];
__device__ float g_pb   [NTOK*NHH*PP];     // [n][h][p]
__device__ float g_att  [BB*NTOK*CC];

// ---------------- GEMM: Y[m,o] = sum_k A[m,k]*W[o,k] + bias[o] ----------------
__global__ __launch_bounds__(256) void gemm_f32(
    const float* __restrict__ A, const float* __restrict__ W,
    const float* __restrict__ bias, float* __restrict__ Y,
    int M, int Nout, int K, int act)
{
    __shared__ float As[8][128];
    __shared__ float Ws[8][128];
    const int tid = threadIdx.x;
    const int m0 = blockIdx.y * 128, n0 = blockIdx.x * 128;
    const int lrow = tid >> 1, lk = (tid & 1) * 4;
    const int ty = tid >> 4, tx = tid & 15;

    const float* Ap = A + (size_t)(m0 + lrow) * K + lk;
    const float* Wp = W + (size_t)(n0 + lrow) * K + lk;

    float acc[8][8];
    #pragma unroll
    for (int i = 0; i < 8; i++)
        #pragma unroll
        for (int j = 0; j < 8; j++) acc[i][j] = 0.f;

    const int kiter = K >> 3;
    for (int kt = 0; kt < kiter; kt++) {
        float4 a4 = *(const float4*)(Ap + kt * 8);
        float4 w4 = *(const float4*)(Wp + kt * 8);
        __syncthreads();
        As[lk+0][lrow] = a4.x; As[lk+1][lrow] = a4.y;
        As[lk+2][lrow] = a4.z; As[lk+3][lrow] = a4.w;
        Ws[lk+0][lrow] = w4.x; Ws[lk+1][lrow] = w4.y;
        Ws[lk+2][lrow] = w4.z; Ws[lk+3][lrow] = w4.w;
        __syncthreads();
        #pragma unroll
        for (int kk = 0; kk < 8; kk++) {
            float a[8], b[8];
            #pragma unroll
            for (int i = 0; i < 8; i++) a[i] = As[kk][ty*8 + i];
            #pragma unroll
            for (int j = 0; j < 8; j++) b[j] = Ws[kk][tx*8 + j];
            #pragma unroll
            for (int i = 0; i < 8; i++)
                #pragma unroll
                for (int j = 0; j < 8; j++) acc[i][j] = fmaf(a[i], b[j], acc[i][j]);
        }
    }
    #pragma unroll
    for (int i = 0; i < 8; i++) {
        int row = m0 + ty*8 + i;
        #pragma unroll
        for (int j = 0; j < 8; j++) {
            int col = n0 + tx*8 + j;
            float r = acc[i][j] + bias[col];
            if (act == 1) r = r * normcdff(r);
            Y[(size_t)row * Nout + col] = r;
        }
    }
}

// ---------------- per-token normalize ----------------
__global__ void normalize_kernel(const float* __restrict__ qe,
                                 const float* __restrict__ temp,
                                 const float* __restrict__ sls)
{
    int bn = blockIdx.x;
    int n  = bn & (NTOK - 1);
    int c  = threadIdx.x;
    int h  = c >> 5;

    float yq = g_qraw [bn*CC + c];
    float yk = g_kvraw[(size_t)bn*2*CC + c];
    float yv = g_kvraw[(size_t)bn*2*CC + CC + c];

    float sq = yq*yq;
    #pragma unroll
    for (int o = 16; o; o >>= 1) sq += __shfl_xor_sync(0xffffffffu, sq, o);
    float qn = yq / fmaxf(sqrtf(sq), 1e-12f);

    float sk = yk*yk;
    #pragma unroll
    for (int o = 16; o; o >>= 1) sk += __shfl_xor_sync(0xffffffffu, sk, o);
    float kn = yk / fmaxf(sqrtf(sk), 1e-12f);

    float scale = log1pf(expf(temp[h])) * sls[n];

    g_qn[bn*CC + c] = qn;
    g_qs[bn*CC + c] = (qn + qe[c]) * scale;
    g_kn[bn*CC + c] = kn;
    g_v [bn*CC + c] = yv;
}

// ---------------- 8x8 avg pool + layernorm ----------------
__global__ void pool_ln_kernel(const float* __restrict__ ng,
                               const float* __restrict__ nb)
{
    int bp = blockIdx.x;               // b*64 + p
    int b  = bp >> 6, p = bp & 63;
    int ph = p >> 3, pw = p & 7;
    int c  = threadIdx.x;

    float s = 0.f;
    for (int r = 0; r < 8; r++)
        #pragma unroll
        for (int q = 0; q < 8; q++) {
            int n = (ph*8 + r) * 64 + pw*8 + q;
            s += g_xs[(size_t)(b*NTOK + n)*CC + c];
        }
    float avg = s * (1.f/64.f);

    float v1 = avg, v2 = avg*avg;
    #pragma unroll
    for (int o = 16; o; o >>= 1) {
        v1 += __shfl_xor_sync(0xffffffffu, v1, o);
        v2 += __shfl_xor_sync(0xffffffffu, v2, o);
    }
    __shared__ float s1[8], s2[8];
    int w = c >> 5, lane = c & 31;
    if (lane == 0) { s1[w] = v1; s2[w] = v2; }
    __syncthreads();
    float m1 = 0.f, m2 = 0.f;
    #pragma unroll
    for (int ww = 0; ww < 8; ww++) { m1 += s1[ww]; m2 += s2[ww]; }
    m1 *= (1.f/256.f); m2 *= (1.f/256.f);
    float var = m2 - m1*m1;
    g_pln[bp*CC + c] = (avg - m1) * rsqrtf(var + 1e-5f) * ng[c] + nb[c];
}

// ---------------- pooled kv projection + k_pool l2norm ----------------
__global__ void kvpool_kernel(const float* __restrict__ kv_w,
                              const float* __restrict__ kv_b)
{
    int bp = blockIdx.x; int b = bp >> 6, p = bp & 63;
    __shared__ __align__(16) float xr[CC];
    int tid = threadIdx.x;             // 0..511
    if (tid < CC) xr[tid] = g_pln[bp*CC + tid];
    __syncthreads();

    int o = tid;
    float acc = kv_b[o];
    const float4* w4 = (const float4*)(kv_w + (size_t)o * CC);
    const float4* x4 = (const float4*)xr;
    #pragma unroll 8
    for (int k = 0; k < 64; k++) {
        float4 w = w4[k], xv = x4[k];
        acc += w.x*xv.x + w.y*xv.y + w.z*xv.z + w.w*xv.w;
    }
    int lane = tid & 31;
    if (o < CC) {
        float s = acc*acc;
        #pragma unroll
        for (int q = 16; q; q >>= 1) s += __shfl_xor_sync(0xffffffffu, s, q);
        float kn = acc / fmaxf(sqrtf(s), 1e-12f);
        int h = o >> 5;
        g_kpT[((b*NHH + h)*HDD + lane)*PP + p] = kn;
    } else {
        int oo = o - CC; int h = oo >> 5, d = oo & 31;
        g_vpl[((b*NHH + h)*PP + p)*HDD + d] = acc;
    }
}

// ---------------- CPB MLP ----------------
__global__ void cpb_kernel(const float* __restrict__ table,
                           const float* __restrict__ w1, const float* __restrict__ b1,
                           const float* __restrict__ w2, const float* __restrict__ b2)
{
    __shared__ float sw1[1024], sb1[512], sw2[4096];
    int tid = threadIdx.x;             // 128
    for (int i = tid; i < 1024; i += 128) sw1[i] = w1[i];
    for (int i = tid; i <  512; i += 128) sb1[i] = b1[i];
    for (int i = tid; i < 4096; i += 128) sw2[i] = w2[i];
    __syncthreads();

    int t = blockIdx.x * 128 + tid;
    float c0 = table[2*t], c1 = table[2*t+1];
    float acc[NHH];
    #pragma unroll
    for (int h = 0; h < NHH; h++) acc[h] = b2[h];
    for (int j = 0; j < 512; j++) {
        float hj = fmaxf(fmaf(c0, sw1[2*j], fmaf(c1, sw1[2*j+1], sb1[j])), 0.f);
        #pragma unroll
        for (int h = 0; h < NHH; h++) acc[h] = fmaf(hj, sw2[h*512 + j], acc[h]);
    }
    #pragma unroll
    for (int h = 0; h < NHH; h++) g_cpb[t*NHH + h] = acc[h];
}

// ---------------- pool bias gather: pb[n][h][p] = cpb[rpi[n][p]][h] ----------------
__global__ void pbias_kernel(const int* __restrict__ rpi)
{
    int n = blockIdx.x, tid = threadIdx.x;     // 512 = h*64+p
    int h = tid >> 6, p = tid & 63;
    int r = rpi[n*PP + p];
    g_pb[(size_t)n*512 + tid] = g_cpb[r*NHH + h];
}

// ---------------- fused attention ----------------
#define SM_KPT 0
#define SM_VPL 16384
#define SM_LT  32768
#define SM_RPB 35072
#define SM_LB  35144
#define SM_QB  35216
#define SM_AP  35728
#define SM_TOT 36752

__global__ __launch_bounds__(512) void attn_kernel(
    const float* __restrict__ rpb_g, const float* __restrict__ lt_g,
    const float* __restrict__ lb_g)
{
    extern __shared__ __align__(16) float sm[];
    float* kpT  = sm + SM_KPT;
    float* vpl  = sm + SM_VPL;
    float* lt   = sm + SM_LT;
    float* rpb  = sm + SM_RPB;
    float* lb   = sm + SM_LB;
    float* qbuf = sm + SM_QB;
    float* apb  = sm + SM_AP;

    int tid = threadIdx.x;
    int b = blockIdx.y, chunk = blockIdx.x;

    for (int i = tid; i < 4096; i += 512) {
        ((float4*)kpT)[i] = ((const float4*)(g_kpT + (size_t)b*16384))[i];
        ((float4*)vpl)[i] = ((const float4*)(g_vpl + (size_t)b*16384))[i];
    }
    for (int i = tid; i < 2304; i += 512) lt[i] = lt_g[i];
    if (tid < 72) { rpb[tid] = rpb_g[tid]; lb[tid] = lb_g[tid]; }
    __syncthreads();

    int w = tid >> 5, lane = tid & 31;
    int h = w & 7, sub = w >> 3;
    const float* kh = kpT + h * (HDD*PP);
    const float* vh = vpl + h * (PP*HDD);

    float rpbl[LL], lbl[LL], ltv[LL];
    #pragma unroll
    for (int l = 0; l < LL; l++) {
        rpbl[l] = rpb[h*LL + l];
        lbl [l] = lb [h*LL + l];
        ltv [l] = lt [h*(HDD*LL) + lane*LL + l];
    }

    for (int t = 0; t < 64; t++) {
        int n = chunk*128 + 2*t + sub;
        int i = n >> 6, j = n & 63;
        size_t base = (size_t)(b*NTOK + n)*CC + h*HDD + lane;
        float qsc = g_qs[base];
        float qnv = g_qn[base];

        qbuf[w*32 + lane] = qsc;
        __syncwarp();

        // local window logits + learnable-token dots
        float kvv[LL];
        #pragma unroll
        for (int l = 0; l < LL; l++) {
            int ii = i + l/3 - 1, jj = j + l%3 - 1;
            bool vl = ((unsigned)ii < 64u) && ((unsigned)jj < 64u);
            kvv[l] = vl ? g_kn[(size_t)(b*NTOK + ii*64 + jj)*CC + h*HDD + lane] : 0.f;
        }
        float el[LL], alt[LL];
        #pragma unroll
        for (int l = 0; l < LL; l++) {
            int ii = i + l/3 - 1, jj = j + l%3 - 1;
            bool vl = ((unsigned)ii < 64u) && ((unsigned)jj < 64u);
            float s = qsc * kvv[l];
            float a = qnv * ltv[l];
            #pragma unroll
            for (int o = 16; o; o >>= 1) {
                s += __shfl_xor_sync(0xffffffffu, s, o);
                a += __shfl_xor_sync(0xffffffffu, a, o);
            }
            el [l] = vl ? (s + rpbl[l]) : -1e30f;
            alt[l] = a + lbl[l];
        }

        // pool logits: lane p and p+32
        float pl0 = 0.f, pl1 = 0.f;
        #pragma unroll
        for (int d = 0; d < 32; d++) {
            float qd = qbuf[w*32 + d];
            pl0 = fmaf(qd, kh[d*64 + lane],      pl0);
            pl1 = fmaf(qd, kh[d*64 + lane + 32], pl1);
        }
        pl0 += g_pb[(size_t)n*512 + h*64 + lane];
        pl1 += g_pb[(size_t)n*512 + h*64 + lane + 32];

        // joint softmax over 9 local (replicated) + 64 pool (distributed)
        float m = fmaxf(pl0, pl1);
        #pragma unroll
        for (int l = 0; l < LL; l++) m = fmaxf(m, el[l]);
        #pragma unroll
        for (int o = 16; o; o >>= 1) m = fmaxf(m, __shfl_xor_sync(0xffffffffu, m, o));
        float ls = 0.f;
        #pragma unroll
        for (int l = 0; l < LL; l++) { el[l] = __expf(el[l] - m); ls += el[l]; }
        float e0 = __expf(pl0 - m), e1 = __expf(pl1 - m);
        float ps = e0 + e1;
        #pragma unroll
        for (int o = 16; o; o >>= 1) ps += __shfl_xor_sync(0xffffffffu, ps, o);
        float inv = 1.f / (ls + ps);

        // local output
        float xo = 0.f;
        #pragma unroll
        for (int l = 0; l < LL; l++) {
            int ii = i + l/3 - 1, jj = j + l%3 - 1;
            if (((unsigned)ii < 64u) && ((unsigned)jj < 64u)) {
                float a = el[l]*inv + alt[l];
                xo = fmaf(a, g_v[(size_t)(b*NTOK + ii*64 + jj)*CC + h*HDD + lane], xo);
            }
        }

        // pool output
        apb[w*64 + lane]      = e0 * inv;
        apb[w*64 + 32 + lane] = e1 * inv;
        __syncwarp();
        #pragma unroll 8
        for (int p = 0; p < 64; p++)
            xo = fmaf(apb[w*64 + p], vh[p*32 + lane], xo);

        g_att[base] = xo;
        __syncwarp();
    }
}

// ---------------- launch ----------------
extern "C" void kernel_launch(void* const* d_in, const int* in_sizes, int n_in,
                              void* d_out, int out_size)
{
    const float* x      = (const float*)d_in[0];
    const int*   rpi    = (const int*)  d_in[1];
    const float* table  = (const float*)d_in[2];
    const float* q_w    = (const float*)d_in[3];
    const float* q_b    = (const float*)d_in[4];
    const float* kv_w   = (const float*)d_in[5];
    const float* kv_b   = (const float*)d_in[6];
    const float* temp   = (const float*)d_in[7];
    const float* qe     = (const float*)d_in[8];
    const float* proj_w = (const float*)d_in[9];
    const float* proj_b = (const float*)d_in[10];
    const float* sr_w   = (const float*)d_in[11];
    const float* sr_b   = (const float*)d_in[12];
    const float* norm_g = (const float*)d_in[13];
    const float* norm_b = (const float*)d_in[14];
    const float* cpb1_w = (const float*)d_in[15];
    const float* cpb1_b = (const float*)d_in[16];
    const float* cpb2_w = (const float*)d_in[17];
    const float* cpb2_b = (const float*)d_in[18];
    const float* rpb    = (const float*)d_in[19];
    const float* lt     = (const float*)d_in[20];
    const float* lb     = (const float*)d_in[21];
    const float* sls    = (const float*)d_in[22];
    float* out = (float*)d_out;

    void *p_qraw, *p_kvraw, *p_xs, *p_att;
    cudaGetSymbolAddress(&p_qraw,  g_qraw);
    cudaGetSymbolAddress(&p_kvraw, g_kvraw);
    cudaGetSymbolAddress(&p_xs,    g_xs);
    cudaGetSymbolAddress(&p_att,   g_att);

    const int M = BB * NTOK;

    gemm_f32<<<dim3(2, M/128), 256>>>(x, q_w,  q_b,  (float*)p_qraw,  M, CC,   CC, 0);
    gemm_f32<<<dim3(4, M/128), 256>>>(x, kv_w, kv_b, (float*)p_kvraw, M, 2*CC, CC, 0);
    gemm_f32<<<dim3(2, M/128), 256>>>(x, sr_w, sr_b, (float*)p_xs,    M, CC,   CC, 1);

    normalize_kernel<<<M, CC>>>(qe, temp, sls);
    pool_ln_kernel<<<BB*PP, CC>>>(norm_g, norm_b);
    kvpool_kernel<<<BB*PP, 512>>>(kv_w, kv_b);
    cpb_kernel<<<TT/128, 128>>>(table, cpb1_w, cpb1_b, cpb2_w, cpb2_b);
    pbias_kernel<<<NTOK, 512>>>(rpi);

    static int smem_set = 0;
    (void)smem_set;
    cudaFuncSetAttribute(attn_kernel, cudaFuncAttributeMaxDynamicSharedMemorySize,
                         SM_TOT * sizeof(float));
    attn_kernel<<<dim3(32, BB), 512, SM_TOT * sizeof(float)>>>(rpb, lt, lb);

    gemm_f32<<<dim3(2, M/128), 256>>>((const float*)p_att, proj_w, proj_b, out, M, CC, CC, 0);
}

// round 3
// speedup vs baseline: 1.0417x; 1.0417x over previous
#include <cuda_runtime.h>

#define BB   4
#define NTOK 4096
#define CC   256
#define NHH  8
#define HDD  32
#define LL   9
#define PP   64
#define TT   4096

// ---------------- scratch ----------------
__device__ float g_qraw [BB*NTOK*CC];
__device__ float g_kvraw[BB*NTOK*2*CC];
__device__ float g_qs   [BB*NTOK*CC];
__device__ float g_qn   [BB*NTOK*CC];
__device__ float g_kn   [BB*NTOK*CC];
__device__ float g_v    [BB*NTOK*CC];
__device__ float g_xs   [BB*NTOK*CC];
__device__ float g_pln  [BB*PP*CC];
__device__ float g_kpT  [BB*NHH*HDD*PP];   // [b][h][d][p]
__device__ float g_vpl  [BB*NHH*PP*HDD];   // [b][h][p][d]
__device__ float g_cpb  [TT*NHH];
__device__ float g_pb   [NTOK*NHH*PP];     // [n][h][p]
__device__ float g_att  [BB*NTOK*CC];

// ---------------- packed f32x2 helpers ----------------
__device__ __forceinline__ void fma2(unsigned long long &d,
                                     unsigned long long a, unsigned long long b){
    asm("fma.rn.f32x2 %0, %1, %2, %0;" : "+l"(d) : "l"(a), "l"(b));
}
__device__ __forceinline__ float2 u2f(unsigned long long u){
    float2 f; asm("mov.b64 {%0, %1}, %2;" : "=f"(f.x), "=f"(f.y) : "l"(u)); return f;
}

// ---------------- GEMM: Y[m,o] = sum_k A[m,k]*W[o,k] + bias[o] ----------------
// 128x128 tile, 256 threads, thread tile 8M(4 pairs) x 8N, packed FFMA2 inner loop.
__global__ __launch_bounds__(256) void gemm_f32(
    const float* __restrict__ A, const float* __restrict__ W,
    const float* __restrict__ bias, float* __restrict__ Y,
    int M, int Nout, int K, int act)
{
    __shared__ __align__(16) float As[8][128];
    __shared__ __align__(16) float Ws[8][256];   // duplicated (w,w) pairs
    const int tid = threadIdx.x;
    const int m0 = blockIdx.y * 128, n0 = blockIdx.x * 128;
    const int lrow = tid >> 1, lk = (tid & 1) * 4;
    const int ty = tid >> 4, tx = tid & 15;

    const float* Ap = A + (size_t)(m0 + lrow) * K + lk;
    const float* Wp = W + (size_t)(n0 + lrow) * K + lk;

    unsigned long long acc[4][8];
    #pragma unroll
    for (int i = 0; i < 4; i++)
        #pragma unroll
        for (int j = 0; j < 8; j++) acc[i][j] = 0ull;

    const int kiter = K >> 3;
    float4 a4 = *(const float4*)Ap;
    float4 w4 = *(const float4*)Wp;

    for (int kt = 0; kt < kiter; kt++) {
        __syncthreads();
        As[lk+0][lrow] = a4.x; As[lk+1][lrow] = a4.y;
        As[lk+2][lrow] = a4.z; As[lk+3][lrow] = a4.w;
        *(float2*)&Ws[lk+0][2*lrow] = make_float2(w4.x, w4.x);
        *(float2*)&Ws[lk+1][2*lrow] = make_float2(w4.y, w4.y);
        *(float2*)&Ws[lk+2][2*lrow] = make_float2(w4.z, w4.z);
        *(float2*)&Ws[lk+3][2*lrow] = make_float2(w4.w, w4.w);
        __syncthreads();
        if (kt + 1 < kiter) {
            a4 = *(const float4*)(Ap + (kt + 1) * 8);
            w4 = *(const float4*)(Wp + (kt + 1) * 8);
        }
        #pragma unroll
        for (int kk = 0; kk < 8; kk++) {
            double2 da0 = *(const double2*)&As[kk][ty*8];
            double2 da1 = *(const double2*)&As[kk][ty*8 + 4];
            unsigned long long a2[4];
            a2[0] = __double_as_longlong(da0.x);
            a2[1] = __double_as_longlong(da0.y);
            a2[2] = __double_as_longlong(da1.x);
            a2[3] = __double_as_longlong(da1.y);
            unsigned long long bb[8];
            #pragma unroll
            for (int u = 0; u < 8; u++)
                bb[u] = __double_as_longlong(*(const double*)&Ws[kk][2*(tx + 16*u)]);
            #pragma unroll
            for (int i = 0; i < 4; i++)
                #pragma unroll
                for (int u = 0; u < 8; u++)
                    fma2(acc[i][u], a2[i], bb[u]);
        }
    }

    #pragma unroll
    for (int i = 0; i < 4; i++) {
        int row = m0 + ty*8 + 2*i;
        #pragma unroll
        for (int u = 0; u < 8; u++) {
            float2 v = u2f(acc[i][u]);
            int col = n0 + tx + u*16;
            float bv = bias[col];
            float r0 = v.x + bv, r1 = v.y + bv;
            if (act == 1) { r0 = r0 * normcdff(r0); r1 = r1 * normcdff(r1); }
            Y[(size_t)row * Nout + col]     = r0;
            Y[(size_t)(row+1) * Nout + col] = r1;
        }
    }
}

// ---------------- per-token normalize ----------------
__global__ void normalize_kernel(const float* __restrict__ qe,
                                 const float* __restrict__ temp,
                                 const float* __restrict__ sls)
{
    int bn = blockIdx.x;
    int n  = bn & (NTOK - 1);
    int c  = threadIdx.x;
    int h  = c >> 5;

    float yq = g_qraw [bn*CC + c];
    float yk = g_kvraw[(size_t)bn*2*CC + c];
    float yv = g_kvraw[(size_t)bn*2*CC + CC + c];

    float sq = yq*yq;
    #pragma unroll
    for (int o = 16; o; o >>= 1) sq += __shfl_xor_sync(0xffffffffu, sq, o);
    float qn = yq / fmaxf(sqrtf(sq), 1e-12f);

    float sk = yk*yk;
    #pragma unroll
    for (int o = 16; o; o >>= 1) sk += __shfl_xor_sync(0xffffffffu, sk, o);
    float kn = yk / fmaxf(sqrtf(sk), 1e-12f);

    float scale = log1pf(expf(temp[h])) * sls[n];

    g_qn[bn*CC + c] = qn;
    g_qs[bn*CC + c] = (qn + qe[c]) * scale;
    g_kn[bn*CC + c] = kn;
    g_v [bn*CC + c] = yv;
}

// ---------------- 8x8 avg pool + layernorm ----------------
__global__ void pool_ln_kernel(const float* __restrict__ ng,
                               const float* __restrict__ nb)
{
    int bp = blockIdx.x;               // b*64 + p
    int b  = bp >> 6, p = bp & 63;
    int ph = p >> 3, pw = p & 7;
    int c  = threadIdx.x;

    float s = 0.f;
    for (int r = 0; r < 8; r++)
        #pragma unroll
        for (int q = 0; q < 8; q++) {
            int n = (ph*8 + r) * 64 + pw*8 + q;
            s += g_xs[(size_t)(b*NTOK + n)*CC + c];
        }
    float avg = s * (1.f/64.f);

    float v1 = avg, v2 = avg*avg;
    #pragma unroll
    for (int o = 16; o; o >>= 1) {
        v1 += __shfl_xor_sync(0xffffffffu, v1, o);
        v2 += __shfl_xor_sync(0xffffffffu, v2, o);
    }
    __shared__ float s1[8], s2[8];
    int w = c >> 5, lane = c & 31;
    if (lane == 0) { s1[w] = v1; s2[w] = v2; }
    __syncthreads();
    float m1 = 0.f, m2 = 0.f;
    #pragma unroll
    for (int ww = 0; ww < 8; ww++) { m1 += s1[ww]; m2 += s2[ww]; }
    m1 *= (1.f/256.f); m2 *= (1.f/256.f);
    float var = m2 - m1*m1;
    g_pln[bp*CC + c] = (avg - m1) * rsqrtf(var + 1e-5f) * ng[c] + nb[c];
}

// ---------------- pooled kv projection + k_pool l2norm ----------------
__global__ void kvpool_kernel(const float* __restrict__ kv_w,
                              const float* __restrict__ kv_b)
{
    int bp = blockIdx.x; int b = bp >> 6, p = bp & 63;
    __shared__ __align__(16) float xr[CC];
    int tid = threadIdx.x;             // 0..511
    if (tid < CC) xr[tid] = g_pln[bp*CC + tid];
    __syncthreads();

    int o = tid;
    float acc = kv_b[o];
    const float4* w4 = (const float4*)(kv_w + (size_t)o * CC);
    const float4* x4 = (const float4*)xr;
    #pragma unroll 8
    for (int k = 0; k < 64; k++) {
        float4 w = w4[k], xv = x4[k];
        acc += w.x*xv.x + w.y*xv.y + w.z*xv.z + w.w*xv.w;
    }
    int lane = tid & 31;
    if (o < CC) {
        float s = acc*acc;
        #pragma unroll
        for (int q = 16; q; q >>= 1) s += __shfl_xor_sync(0xffffffffu, s, q);
        float kn = acc / fmaxf(sqrtf(s), 1e-12f);
        int h = o >> 5;
        g_kpT[((b*NHH + h)*HDD + lane)*PP + p] = kn;
    } else {
        int oo = o - CC; int h = oo >> 5, d = oo & 31;
        g_vpl[((b*NHH + h)*PP + p)*HDD + d] = acc;
    }
}

// ---------------- CPB MLP ----------------
__global__ void cpb_kernel(const float* __restrict__ table,
                           const float* __restrict__ w1, const float* __restrict__ b1,
                           const float* __restrict__ w2, const float* __restrict__ b2)
{
    __shared__ float sw1[1024], sb1[512], sw2[4096];
    int tid = threadIdx.x;             // 128
    for (int i = tid; i < 1024; i += 128) sw1[i] = w1[i];
    for (int i = tid; i <  512; i += 128) sb1[i] = b1[i];
    for (int i = tid; i < 4096; i += 128) sw2[i] = w2[i];
    __syncthreads();

    int t = blockIdx.x * 128 + tid;
    float c0 = table[2*t], c1 = table[2*t+1];
    float acc[NHH];
    #pragma unroll
    for (int h = 0; h < NHH; h++) acc[h] = b2[h];
    for (int j = 0; j < 512; j++) {
        float hj = fmaxf(fmaf(c0, sw1[2*j], fmaf(c1, sw1[2*j+1], sb1[j])), 0.f);
        #pragma unroll
        for (int h = 0; h < NHH; h++) acc[h] = fmaf(hj, sw2[h*512 + j], acc[h]);
    }
    #pragma unroll
    for (int h = 0; h < NHH; h++) g_cpb[t*NHH + h] = acc[h];
}

// ---------------- pool bias gather ----------------
__global__ void pbias_kernel(const int* __restrict__ rpi)
{
    int n = blockIdx.x, tid = threadIdx.x;     // 512 = h*64+p
    int h = tid >> 6, p = tid & 63;
    int r = rpi[n*PP + p];
    g_pb[(size_t)n*512 + tid] = g_cpb[r*NHH + h];
}

// ---------------- fused attention ----------------
#define SM_KPT 0
#define SM_VPL 16384
#define SM_LT  32768
#define SM_RPB 35072
#define SM_LB  35144
#define SM_QB  35216
#define SM_AP  35728
#define SM_TOT 36752

__global__ __launch_bounds__(512) void attn_kernel(
    const float* __restrict__ rpb_g, const float* __restrict__ lt_g,
    const float* __restrict__ lb_g)
{
    extern __shared__ __align__(16) float sm[];
    float* kpT  = sm + SM_KPT;
    float* vpl  = sm + SM_VPL;
    float* lt   = sm + SM_LT;
    float* rpb  = sm + SM_RPB;
    float* lb   = sm + SM_LB;
    float* qbuf = sm + SM_QB;
    float* apb  = sm + SM_AP;

    int tid = threadIdx.x;
    int b = blockIdx.y, chunk = blockIdx.x;

    for (int i = tid; i < 4096; i += 512) {
        ((float4*)kpT)[i] = ((const float4*)(g_kpT + (size_t)b*16384))[i];
        ((float4*)vpl)[i] = ((const float4*)(g_vpl + (size_t)b*16384))[i];
    }
    for (int i = tid; i < 2304; i += 512) lt[i] = lt_g[i];
    if (tid < 72) { rpb[tid] = rpb_g[tid]; lb[tid] = lb_g[tid]; }
    __syncthreads();

    int w = tid >> 5, lane = tid & 31;
    int h = w & 7, sub = w >> 3;
    const float* kh = kpT + h * (HDD*PP);
    const float* vh = vpl + h * (PP*HDD);

    float rpbl[LL], lbl[LL], ltv[LL];
    #pragma unroll
    for (int l = 0; l < LL; l++) {
        rpbl[l] = rpb[h*LL + l];
        lbl [l] = lb [h*LL + l];
        ltv [l] = lt [h*(HDD*LL) + lane*LL + l];
    }

    for (int t = 0; t < 64; t++) {
        int n = chunk*128 + 2*t + sub;
        int i = n >> 6, j = n & 63;
        size_t base = (size_t)(b*NTOK + n)*CC + h*HDD + lane;
        float qsc = g_qs[base];
        float qnv = g_qn[base];

        qbuf[w*32 + lane] = qsc;
        __syncwarp();

        float kvv[LL];
        #pragma unroll
        for (int l = 0; l < LL; l++) {
            int ii = i + l/3 - 1, jj = j + l%3 - 1;
            bool vl = ((unsigned)ii < 64u) && ((unsigned)jj < 64u);
            kvv[l] = vl ? g_kn[(size_t)(b*NTOK + ii*64 + jj)*CC + h*HDD + lane] : 0.f;
        }
        float el[LL], alt[LL];
        #pragma unroll
        for (int l = 0; l < LL; l++) {
            int ii = i + l/3 - 1, jj = j + l%3 - 1;
            bool vl = ((unsigned)ii < 64u) && ((unsigned)jj < 64u);
            float s = qsc * kvv[l];
            float a = qnv * ltv[l];
            #pragma unroll
            for (int o = 16; o; o >>= 1) {
                s += __shfl_xor_sync(0xffffffffu, s, o);
                a += __shfl_xor_sync(0xffffffffu, a, o);
            }
            el [l] = vl ? (s + rpbl[l]) : -1e30f;
            alt[l] = a + lbl[l];
        }

        float pl0 = 0.f, pl1 = 0.f;
        #pragma unroll
        for (int d = 0; d < 32; d++) {
            float qd = qbuf[w*32 + d];
            pl0 = fmaf(qd, kh[d*64 + lane],      pl0);
            pl1 = fmaf(qd, kh[d*64 + lane + 32], pl1);
        }
        pl0 += g_pb[(size_t)n*512 + h*64 + lane];
        pl1 += g_pb[(size_t)n*512 + h*64 + lane + 32];

        float m = fmaxf(pl0, pl1);
        #pragma unroll
        for (int l = 0; l < LL; l++) m = fmaxf(m, el[l]);
        #pragma unroll
        for (int o = 16; o; o >>= 1) m = fmaxf(m, __shfl_xor_sync(0xffffffffu, m, o));
        float ls = 0.f;
        #pragma unroll
        for (int l = 0; l < LL; l++) { el[l] = __expf(el[l] - m); ls += el[l]; }
        float e0 = __expf(pl0 - m), e1 = __expf(pl1 - m);
        float ps = e0 + e1;
        #pragma unroll
        for (int o = 16; o; o >>= 1) ps += __shfl_xor_sync(0xffffffffu, ps, o);
        float inv = 1.f / (ls + ps);

        float xo = 0.f;
        #pragma unroll
        for (int l = 0; l < LL; l++) {
            int ii = i + l/3 - 1, jj = j + l%3 - 1;
            if (((unsigned)ii < 64u) && ((unsigned)jj < 64u)) {
                float a = el[l]*inv + alt[l];
                xo = fmaf(a, g_v[(size_t)(b*NTOK + ii*64 + jj)*CC + h*HDD + lane], xo);
            }
        }

        apb[w*64 + lane]      = e0 * inv;
        apb[w*64 + 32 + lane] = e1 * inv;
        __syncwarp();
        #pragma unroll 8
        for (int p = 0; p < 64; p++)
            xo = fmaf(apb[w*64 + p], vh[p*32 + lane], xo);

        g_att[base] = xo;
        __syncwarp();
    }
}

// ---------------- launch ----------------
extern "C" void kernel_launch(void* const* d_in, const int* in_sizes, int n_in,
                              void* d_out, int out_size)
{
    const float* x      = (const float*)d_in[0];
    const int*   rpi    = (const int*)  d_in[1];
    const float* table  = (const float*)d_in[2];
    const float* q_w    = (const float*)d_in[3];
    const float* q_b    = (const float*)d_in[4];
    const float* kv_w   = (const float*)d_in[5];
    const float* kv_b   = (const float*)d_in[6];
    const float* temp   = (const float*)d_in[7];
    const float* qe     = (const float*)d_in[8];
    const float* proj_w = (const float*)d_in[9];
    const float* proj_b = (const float*)d_in[10];
    const float* sr_w   = (const float*)d_in[11];
    const float* sr_b   = (const float*)d_in[12];
    const float* norm_g = (const float*)d_in[13];
    const float* norm_b = (const float*)d_in[14];
    const float* cpb1_w = (const float*)d_in[15];
    const float* cpb1_b = (const float*)d_in[16];
    const float* cpb2_w = (const float*)d_in[17];
    const float* cpb2_b = (const float*)d_in[18];
    const float* rpb    = (const float*)d_in[19];
    const float* lt     = (const float*)d_in[20];
    const float* lb     = (const float*)d_in[21];
    const float* sls    = (const float*)d_in[22];
    float* out = (float*)d_out;

    void *p_qraw, *p_kvraw, *p_xs, *p_att;
    cudaGetSymbolAddress(&p_qraw,  g_qraw);
    cudaGetSymbolAddress(&p_kvraw, g_kvraw);
    cudaGetSymbolAddress(&p_xs,    g_xs);
    cudaGetSymbolAddress(&p_att,   g_att);

    const int M = BB * NTOK;

    gemm_f32<<<dim3(2, M/128), 256>>>(x, q_w,  q_b,  (float*)p_qraw,  M, CC,   CC, 0);
    gemm_f32<<<dim3(4, M/128), 256>>>(x, kv_w, kv_b, (float*)p_kvraw, M, 2*CC, CC, 0);
    gemm_f32<<<dim3(2, M/128), 256>>>(x, sr_w, sr_b, (float*)p_xs,    M, CC,   CC, 1);

    normalize_kernel<<<M, CC>>>(qe, temp, sls);
    pool_ln_kernel<<<BB*PP, CC>>>(norm_g, norm_b);
    kvpool_kernel<<<BB*PP, 512>>>(kv_w, kv_b);
    cpb_kernel<<<TT/128, 128>>>(table, cpb1_w, cpb1_b, cpb2_w, cpb2_b);
    pbias_kernel<<<NTOK, 512>>>(rpi);

    cudaFuncSetAttribute(attn_kernel, cudaFuncAttributeMaxDynamicSharedMemorySize,
                         SM_TOT * sizeof(float));
    attn_kernel<<<dim3(32, BB), 512, SM_TOT * sizeof(float)>>>(rpb, lt, lb);

    gemm_f32<<<dim3(2, M/128), 256>>>((const float*)p_att, proj_w, proj_b, out, M, CC, CC, 0);
}